// round 4
// baseline (speedup 1.0000x reference)
#include <cuda_runtime.h>
#include <cstdint>

#define BB   16
#define HH   512
#define WW   512
#define HWSZ (HH*WW)
#define KSEL 262          // int(512*512*0.001)
#define NBIN 4096
#define CAP  65536

// ---------------- scratch (device globals; no allocation allowed) ----------------
__device__ float  g_guid [BB*HWSZ];
__device__ float  g_hmin1[BB*HWSZ];
__device__ float  g_dc1  [BB*HWSZ];
__device__ float  g_hmin2[BB*HWSZ];
__device__ float  g_p    [BB*HWSZ];
__device__ float2 g_ab   [BB*HWSZ];

__device__ unsigned g_hist4k[BB*NBIN];
__device__ int      g_binlo[BB];
__device__ int      g_rem[BB];
__device__ int      g_ccount[BB];
__device__ unsigned long long g_cand[(size_t)BB*CAP];
__device__ float    g_mapA[BB*3];
__device__ float    g_invAh[BB*3];

// ---------- stage 1: guidance + channel-min + horizontal min15 (float4) ----------
// blockIdx.x==0 blocks also zero the per-batch selection state (replaces k_init).
__global__ void k_prep_minh(const float* __restrict__ x){
    int row = blockIdx.x, b = blockIdx.y, t = threadIdx.x;  // t < 128
    if (row == 0){
        for (int i = t; i < NBIN; i += 128) g_hist4k[b*NBIN + i] = 0;
        if (t == 0) g_ccount[b] = 0;
    }
    const float4* xr = (const float4*)(x + (size_t)b*3*HWSZ + (size_t)row*WW);
    float4 r  = xr[t];
    float4 g  = xr[HWSZ/4 + t];
    float4 bl = xr[2*(HWSZ/4) + t];
    size_t o4 = ((size_t)b*HWSZ + (size_t)row*WW) >> 2;
    float4 gv;
    gv.x = (0.2989f*r.x + 0.587f*g.x + 0.114f*bl.x + 1.0f)*0.5f;
    gv.y = (0.2989f*r.y + 0.587f*g.y + 0.114f*bl.y + 1.0f)*0.5f;
    gv.z = (0.2989f*r.z + 0.587f*g.z + 0.114f*bl.z + 1.0f)*0.5f;
    gv.w = (0.2989f*r.w + 0.587f*g.w + 0.114f*bl.w + 1.0f)*0.5f;
    ((float4*)g_guid)[o4 + t] = gv;
    float4 mn;
    mn.x = (fminf(r.x, fminf(g.x, bl.x)) + 1.0f)*0.5f;
    mn.y = (fminf(r.y, fminf(g.y, bl.y)) + 1.0f)*0.5f;
    mn.z = (fminf(r.z, fminf(g.z, bl.z)) + 1.0f)*0.5f;
    mn.w = (fminf(r.w, fminf(g.w, bl.w)) + 1.0f)*0.5f;
    __shared__ float s[WW + 32];
    *(float4*)&s[16 + 4*t] = mn;
    if (t < 7){ s[9+t] = 1.0f; s[528+t] = 1.0f; }
    __syncthreads();
    const float* a = &s[4*t + 9];
    float c12 = a[3];
    #pragma unroll
    for (int j=4; j<=14; j++) c12 = fminf(c12, a[j]);
    float4 o;
    o.x = fminf(fminf(a[0], a[1]), fminf(a[2], c12));
    o.y = fminf(fminf(a[1], a[2]), fminf(c12, a[15]));
    o.z = fminf(a[2], fminf(c12, fminf(a[15], a[16])));
    o.w = fminf(c12, fminf(a[15], fminf(a[16], a[17])));
    ((float4*)g_hmin1)[o4 + t] = o;
}

// ---------- vertical min15 -> dc1 + fused 4096-bin histogram ----------
__global__ void k_minv0_hist(){
    int b  = blockIdx.z;
    int bx = blockIdx.x*32, by = blockIdx.y*128;
    int tx = threadIdx.x, ty = threadIdx.y;
    int tid = ty*32 + tx;
    __shared__ float s[142][32];
    __shared__ unsigned shh[NBIN];
    for (int i = tid; i < NBIN; i += 256) shh[i] = 0;
    const float* sb = g_hmin1 + (size_t)b*HWSZ;
    for (int i = tid; i < 142*8; i += 256){
        int rr = i >> 3, c4 = i & 7;
        int gy = by - 7 + rr;
        float4 v = (gy >= 0 && gy < HH)
                   ? ((const float4*)(sb + (size_t)gy*WW + bx))[c4]
                   : make_float4(1,1,1,1);
        *(float4*)&s[rr][c4*4] = v;
    }
    __syncthreads();
    float* db = g_dc1 + (size_t)b*HWSZ;
    #pragma unroll
    for (int o = 0; o < 16; o++){
        int ry = ty + o*8;
        float m = s[ry][tx];
        #pragma unroll
        for (int i = 1; i < 15; i++) m = fminf(m, s[ry+i][tx]);
        db[(size_t)(by+ry)*WW + bx + tx] = m;
        unsigned bin = min(4095u, (unsigned)(m * 16384.0f));
        unsigned mm = __match_any_sync(0xffffffffu, bin);
        if (tx == __ffs(mm)-1) atomicAdd(&shh[bin], (unsigned)__popc(mm));
    }
    __syncthreads();
    unsigned* gh = g_hist4k + b*NBIN;
    for (int i = tid; i < NBIN; i += 256)
        if (shh[i]) atomicAdd(&gh[i], shh[i]);
}

// ---------- scan histogram (parallel) ----------
__global__ void k_scan(){
    int b = blockIdx.x, t = threadIdx.x;
    const unsigned* h = g_hist4k + b*NBIN;
    int hi_bin = 4095 - t*16;
    unsigned v[16]; unsigned sum = 0;
    #pragma unroll
    for (int i = 0; i < 16; i++){ v[i] = h[hi_bin - i]; sum += v[i]; }
    // block-wide exclusive prefix of sum (descending-bin order)
    unsigned lane = t & 31, wid = t >> 5;
    unsigned s = sum;
    #pragma unroll
    for (int o = 1; o < 32; o <<= 1){
        unsigned n = __shfl_up_sync(0xffffffffu, s, o);
        if (lane >= o) s += n;
    }
    __shared__ unsigned wsum[8];
    if (lane == 31) wsum[wid] = s;
    __syncthreads();
    unsigned woff = 0;
    #pragma unroll
    for (int w = 0; w < 8; w++) if (w < (int)wid) woff += wsum[w];
    unsigned cum = s + woff - sum;   // exclusive prefix
    #pragma unroll
    for (int i = 0; i < 16; i++){
        unsigned c = v[i];
        if (cum < KSEL && cum + c >= KSEL){
            g_binlo[b] = hi_bin - i;
            g_rem[b]   = KSEL - (int)cum;
        }
        cum += c;
    }
}

// ---------- collect candidates (bin >= binlo) ----------
__global__ void k_collect(){
    int b = blockIdx.y;
    int binlo = g_binlo[b];
    const float4* dc = (const float4*)(g_dc1 + (size_t)b*HWSZ);
    unsigned long long* cb = g_cand + (size_t)b*CAP;
    for (int i = blockIdx.x*256 + threadIdx.x; i < HWSZ/4; i += 64*256){
        float4 v = dc[i];
        float vv[4] = {v.x, v.y, v.z, v.w};
        #pragma unroll
        for (int k = 0; k < 4; k++){
            unsigned bin = min(4095u, (unsigned)(vv[k]*16384.0f));
            if ((int)bin >= binlo){
                int pos = atomicAdd(&g_ccount[b], 1);
                if (pos < CAP)
                    cb[pos] = ((unsigned long long)__float_as_uint(vv[k]) << 32) | (unsigned)(i*4 + k);
            }
        }
    }
}

// ---------- exact select over candidates: radix for tau, tie cut, argmax ----------
__global__ void k_select(const float* __restrict__ x){
    int b = blockIdx.x, tid = threadIdx.x;
    int n = min(g_ccount[b], CAP);
    const unsigned long long* cand = g_cand + (size_t)b*CAP;

    __shared__ unsigned hist[256];
    __shared__ unsigned s_pref;
    __shared__ int s_rem;
    if (tid == 0){ s_pref = 0; s_rem = KSEL; }
    __syncthreads();
    for (int shift = 24; shift >= 0; shift -= 8){
        hist[tid] = 0;
        __syncthreads();
        unsigned pref = s_pref;
        for (int j = tid; j < n; j += 256){
            unsigned bits = (unsigned)(cand[j] >> 32);
            if (shift == 24 || (bits >> (shift+8)) == pref)
                atomicAdd(&hist[(bits >> shift) & 255u], 1u);
        }
        __syncthreads();
        if (tid == 0){
            int rem = s_rem, cum = 0, chosen = 0;
            for (int bin = 255; bin >= 0; --bin){
                int c = (int)hist[bin];
                if (cum + c >= rem){ chosen = bin; break; }
                cum += c;
            }
            s_pref = (pref << 8) | (unsigned)chosen;
            s_rem  = rem - cum;
        }
        __syncthreads();
    }
    unsigned tau = s_pref;
    int m = s_rem;

    __shared__ int s_cnt;
    int lo = 0, hi = HWSZ - 1;
    while (lo < hi){
        int mid = (lo + hi) >> 1;
        if (tid == 0) s_cnt = 0;
        __syncthreads();
        int local = 0;
        for (int j = tid; j < n; j += 256){
            unsigned long long e = cand[j];
            if ((unsigned)(e >> 32) == tau && (int)(e & 0xffffffffu) <= mid) local++;
        }
        if (local) atomicAdd(&s_cnt, local);
        __syncthreads();
        int c = s_cnt;
        __syncthreads();
        if (c >= m) hi = mid; else lo = mid + 1;
    }
    int idx_cut = lo;

    float bi = -1e30f, bd = -1e30f; int bix = 0x7fffffff;
    const float* xb = x + (size_t)b*3*HWSZ;
    for (int j = tid; j < n; j += 256){
        unsigned long long e = cand[j];
        unsigned bits = (unsigned)(e >> 32);
        int idx = (int)(e & 0xffffffffu);
        if (bits > tau || (bits == tau && idx <= idx_cut)){
            float r  = (xb[idx]        + 1.0f)*0.5f;
            float g  = (xb[HWSZ+idx]   + 1.0f)*0.5f;
            float bl = (xb[2*HWSZ+idx] + 1.0f)*0.5f;
            float inten = 0.2989f*r + 0.587f*g + 0.114f*bl;
            float dv = __uint_as_float(bits);
            bool better = (inten > bi) ||
                          (inten == bi && (dv > bd || (dv == bd && idx < bix)));
            if (better){ bi = inten; bd = dv; bix = idx; }
        }
    }
    __shared__ float sI[256], sD[256];
    __shared__ int   sX[256];
    sI[tid] = bi; sD[tid] = bd; sX[tid] = bix;
    __syncthreads();
    for (int s = 128; s > 0; s >>= 1){
        if (tid < s){
            float oi = sI[tid+s], od = sD[tid+s]; int ox = sX[tid+s];
            bool better = (oi > sI[tid]) ||
                          (oi == sI[tid] && (od > sD[tid] || (od == sD[tid] && ox < sX[tid])));
            if (better){ sI[tid] = oi; sD[tid] = od; sX[tid] = ox; }
        }
        __syncthreads();
    }
    if (tid < 3){
        int idx = sX[0];
        float a  = (xb[(size_t)tid*HWSZ + idx] + 1.0f)*0.5f;
        float mA = a*2.0f - 1.0f;
        g_mapA[b*3+tid]  = mA;
        g_invAh[b*3+tid] = 1.0f / ((mA + 1.0f)*0.5f);
    }
}

// ---------- ratio channel-min + horizontal min15 (float4) ----------
__global__ void k_ratio_minh(const float* __restrict__ x){
    int row = blockIdx.x, b = blockIdx.y, t = threadIdx.x;  // t < 128
    const float4* xr = (const float4*)(x + (size_t)b*3*HWSZ + (size_t)row*WW);
    float inv0 = g_invAh[b*3], inv1 = g_invAh[b*3+1], inv2 = g_invAh[b*3+2];
    float4 r  = xr[t];
    float4 g  = xr[HWSZ/4 + t];
    float4 bl = xr[2*(HWSZ/4) + t];
    float4 mn;
    mn.x = fminf((r.x+1.0f)*0.5f*inv0, fminf((g.x+1.0f)*0.5f*inv1, (bl.x+1.0f)*0.5f*inv2));
    mn.y = fminf((r.y+1.0f)*0.5f*inv0, fminf((g.y+1.0f)*0.5f*inv1, (bl.y+1.0f)*0.5f*inv2));
    mn.z = fminf((r.z+1.0f)*0.5f*inv0, fminf((g.z+1.0f)*0.5f*inv1, (bl.z+1.0f)*0.5f*inv2));
    mn.w = fminf((r.w+1.0f)*0.5f*inv0, fminf((g.w+1.0f)*0.5f*inv1, (bl.w+1.0f)*0.5f*inv2));
    __shared__ float s[WW + 32];
    *(float4*)&s[16 + 4*t] = mn;
    if (t < 7){ s[9+t] = 1.0f; s[528+t] = 1.0f; }
    __syncthreads();
    const float* a = &s[4*t + 9];
    float c12 = a[3];
    #pragma unroll
    for (int j=4; j<=14; j++) c12 = fminf(c12, a[j]);
    float4 o;
    o.x = fminf(fminf(a[0], a[1]), fminf(a[2], c12));
    o.y = fminf(fminf(a[1], a[2]), fminf(c12, a[15]));
    o.z = fminf(a[2], fminf(c12, fminf(a[15], a[16])));
    o.w = fminf(c12, fminf(a[15], fminf(a[16], a[17])));
    ((float4*)g_hmin2)[(((size_t)b*HWSZ + (size_t)row*WW) >> 2) + t] = o;
}

// ---------- vertical min15 -> trans_raw p ----------
__global__ void k_minv1(){
    int b  = blockIdx.z;
    int bx = blockIdx.x*32, by = blockIdx.y*128;
    int tx = threadIdx.x, ty = threadIdx.y;
    int tid = ty*32 + tx;
    __shared__ float s[142][32];
    const float* sb = g_hmin2 + (size_t)b*HWSZ;
    for (int i = tid; i < 142*8; i += 256){
        int rr = i >> 3, c4 = i & 7;
        int gy = by - 7 + rr;
        float4 v = (gy >= 0 && gy < HH)
                   ? ((const float4*)(sb + (size_t)gy*WW + bx))[c4]
                   : make_float4(1,1,1,1);
        *(float4*)&s[rr][c4*4] = v;
    }
    __syncthreads();
    float* db = g_p + (size_t)b*HWSZ;
    #pragma unroll
    for (int o = 0; o < 16; o++){
        int ry = ty + o*8;
        float m = s[ry][tx];
        #pragma unroll
        for (int i = 1; i < 15; i++) m = fminf(m, s[ry+i][tx]);
        db[(size_t)(by+ry)*WW + bx + tx] = 1.0f - 0.95f*m;
    }
}

// ---------- fused guided-filter pass 1: 2D box of (I,p,Ip,II) -> (a,b) ----------
// One thread per column (288 = 256 outputs + 16 halo each side), running vertical
// window sums in registers; per-row horizontal sums via 8-wide group sums in smem.
__global__ void k_gf1(){
    int b   = blockIdx.z;
    int bx0 = blockIdx.x*256;
    int y0  = blockIdx.y*64;
    int tid = threadIdx.x;                 // 0..287
    int xcol = bx0 + tid - 16;
    bool xok = (xcol >= 0 && xcol < WW);
    const float* Ib = g_guid + (size_t)b*HWSZ;
    const float* pb = g_p    + (size_t)b*HWSZ;
    float sI=0.f, sp=0.f, sIp=0.f, sII=0.f;
    int ylo = y0-15 < 0 ? 0 : y0-15;
    int yhi = y0+15 > HH-1 ? HH-1 : y0+15;
    if (xok){
        for (int yy = ylo; yy <= yhi; ++yy){
            float Iv = Ib[(size_t)yy*WW + xcol];
            float pv = pb[(size_t)yy*WW + xcol];
            sI += Iv; sp += pv; sIp += Iv*pv; sII += Iv*Iv;
        }
    }
    __shared__ float vI[288], vp[288], vIp[288], vII[288];
    __shared__ float gI[36], gp2[36], gIp[36], gII[36];
    float2* db = g_ab + (size_t)b*HWSZ;
    bool outth = (tid >= 16 && tid < 272);
    float fnx = 0.f;
    if (outth){
        int gx = xcol;
        fnx = (float)(min(gx+15, WW-1) - max(gx-15, 0) + 1);
    }
    for (int j = 0; j < 64; ++j){
        int y = y0 + j;
        vI[tid]=sI; vp[tid]=sp; vIp[tid]=sIp; vII[tid]=sII;
        __syncthreads();
        if (tid < 144){
            int ch = tid >> 5 <= 4 ? tid/36 : 0;  // overwritten below; keep simple
        }
        if (tid < 144){
            int ch = tid / 36, g = tid - ch*36;
            const float* src = (ch==0)?vI:(ch==1)?vp:(ch==2)?vIp:vII;
            float*       dst = (ch==0)?gI:(ch==1)?gp2:(ch==2)?gIp:gII;
            float ssum = 0.f;
            #pragma unroll
            for (int k=0;k<8;k++) ssum += src[g*8+k];
            dst[g] = ssum;
        }
        __syncthreads();
        if (outth){
            int L = tid-15, R = tid+15;
            int gL = (L+7)>>3, gR = (R+1)>>3;
            float hI=0.f,hp=0.f,hIp=0.f,hII=0.f;
            for (int g=gL; g<gR; ++g){ hI+=gI[g]; hp+=gp2[g]; hIp+=gIp[g]; hII+=gII[g]; }
            for (int k=L; k<gL*8; ++k){ hI+=vI[k]; hp+=vp[k]; hIp+=vIp[k]; hII+=vII[k]; }
            for (int k=gR*8; k<=R; ++k){ hI+=vI[k]; hp+=vp[k]; hIp+=vIp[k]; hII+=vII[k]; }
            float fny = (float)(min(y+15, HH-1) - max(y-15, 0) + 1);
            float nInv = __frcp_rn(fnx*fny);
            float mI=hI*nInv, mp=hp*nInv, mIp=hIp*nInv, mII=hII*nInv;
            float cov = mIp - mI*mp;
            float var = mII - mI*mI;
            float a   = cov / (var + 1e-3f);
            db[(size_t)y*WW + xcol] = make_float2(a, mp - a*mI);
        }
        __syncthreads();
        if (xok){
            int yin = y+16, yout = y-15;
            if (yin < HH){
                float Iv = Ib[(size_t)yin*WW + xcol], pv = pb[(size_t)yin*WW + xcol];
                sI += Iv; sp += pv; sIp += Iv*pv; sII += Iv*Iv;
            }
            if (yout >= 0){
                float Iv = Ib[(size_t)yout*WW + xcol], pv = pb[(size_t)yout*WW + xcol];
                sI -= Iv; sp -= pv; sIp -= Iv*pv; sII -= Iv*Iv;
            }
        }
    }
}

// ---------- fused guided-filter pass 2: 2D box of (a,b) -> T, J, A ----------
__global__ void k_gf2(const float* __restrict__ x, float* __restrict__ out){
    int b   = blockIdx.z;
    int bx0 = blockIdx.x*256;
    int y0  = blockIdx.y*64;
    int tid = threadIdx.x;                 // 0..287
    int xcol = bx0 + tid - 16;
    bool xok = (xcol >= 0 && xcol < WW);
    const float2* ab = g_ab + (size_t)b*HWSZ;
    float sa=0.f, sb=0.f;
    int ylo = y0-15 < 0 ? 0 : y0-15;
    int yhi = y0+15 > HH-1 ? HH-1 : y0+15;
    if (xok){
        for (int yy = ylo; yy <= yhi; ++yy){
            float2 v = ab[(size_t)yy*WW + xcol];
            sa += v.x; sb += v.y;
        }
    }
    __shared__ float va[288], vb[288];
    __shared__ float ga[36], gb[36];
    bool outth = (tid >= 16 && tid < 272);
    float fnx = 0.f;
    if (outth){
        int gx = xcol;
        fnx = (float)(min(gx+15, WW-1) - max(gx-15, 0) + 1);
    }
    float mA0 = g_mapA[b*3], mA1 = g_mapA[b*3+1], mA2 = g_mapA[b*3+2];
    const float* Ib = g_guid + (size_t)b*HWSZ;
    const float* xb = x + (size_t)b*3*HWSZ;
    float* outJ = out;
    float* outT = out + (size_t)BB*3*HWSZ;
    float* outA = out + (size_t)BB*3*HWSZ + (size_t)BB*HWSZ;
    for (int j = 0; j < 64; ++j){
        int y = y0 + j;
        va[tid]=sa; vb[tid]=sb;
        __syncthreads();
        if (tid < 72){
            int ch = tid / 36, g = tid - ch*36;
            const float* src = (ch==0)?va:vb;
            float*       dst = (ch==0)?ga:gb;
            float ssum = 0.f;
            #pragma unroll
            for (int k=0;k<8;k++) ssum += src[g*8+k];
            dst[g] = ssum;
        }
        __syncthreads();
        if (outth){
            int L = tid-15, R = tid+15;
            int gL = (L+7)>>3, gR = (R+1)>>3;
            float ha=0.f, hb=0.f;
            for (int g=gL; g<gR; ++g){ ha+=ga[g]; hb+=gb[g]; }
            for (int k=L; k<gL*8; ++k){ ha+=va[k]; hb+=vb[k]; }
            for (int k=gR*8; k<=R; ++k){ ha+=va[k]; hb+=vb[k]; }
            float fny = (float)(min(y+15, HH-1) - max(y-15, 0) + 1);
            float nInv = __frcp_rn(fnx*fny);
            size_t idx = (size_t)y*WW + xcol;
            float I = Ib[idx];
            float T = (ha*nInv)*I + hb*nInv;
            outT[(size_t)b*HWSZ + idx] = T;
            float invT = 1.0f / T;
            float x0 = xb[idx], x1 = xb[HWSZ+idx], x2 = xb[2*HWSZ+idx];
            size_t jb = (size_t)b*3*HWSZ + idx;
            outJ[jb]        = ((x0+1.0f)*0.5f - mA0)*invT + mA0;
            outJ[jb+HWSZ]   = ((x1+1.0f)*0.5f - mA1)*invT + mA1;
            outJ[jb+2*HWSZ] = ((x2+1.0f)*0.5f - mA2)*invT + mA2;
            outA[jb]        = mA0;
            outA[jb+HWSZ]   = mA1;
            outA[jb+2*HWSZ] = mA2;
        }
        __syncthreads();
        if (xok){
            int yin = y+16, yout = y-15;
            if (yin < HH){
                float2 v = ab[(size_t)yin*WW + xcol];
                sa += v.x; sb += v.y;
            }
            if (yout >= 0){
                float2 v = ab[(size_t)yout*WW + xcol];
                sa -= v.x; sb -= v.y;
            }
        }
    }
}

// ---------------- launch ----------------
extern "C" void kernel_launch(void* const* d_in, const int* in_sizes, int n_in,
                              void* d_out, int out_size){
    (void)in_sizes; (void)n_in; (void)out_size;
    const float* x = (const float*)d_in[0];
    float* out = (float*)d_out;

    k_prep_minh<<<dim3(HH, BB), 128>>>(x);
    k_minv0_hist<<<dim3(16, 4, BB), dim3(32, 8)>>>();
    k_scan<<<BB, 256>>>();
    k_collect<<<dim3(64, BB), 256>>>();
    k_select<<<BB, 256>>>(x);

    k_ratio_minh<<<dim3(HH, BB), 128>>>(x);
    k_minv1<<<dim3(16, 4, BB), dim3(32, 8)>>>();

    k_gf1<<<dim3(2, 8, BB), 288>>>();
    k_gf2<<<dim3(2, 8, BB), 288>>>(x, out);
}

// round 5
// speedup vs baseline: 1.7013x; 1.7013x over previous
#include <cuda_runtime.h>
#include <cstdint>

#define BB   16
#define HH   512
#define WW   512
#define HWSZ (HH*WW)
#define KSEL 262          // int(512*512*0.001)
#define NBIN 4096
#define CAP  65536

// ---------------- scratch (device globals; no allocation allowed) ----------------
__device__ float  g_guid [BB*HWSZ];
__device__ float  g_hmin1[BB*HWSZ];
__device__ float  g_dc1  [BB*HWSZ];
__device__ float  g_hmin2[BB*HWSZ];
__device__ float  g_p    [BB*HWSZ];
__device__ float4 g_b4h  [BB*HWSZ];
__device__ float2 g_ab   [BB*HWSZ];
__device__ float2 g_abh  [BB*HWSZ];

__device__ unsigned g_hist4k[BB*NBIN];
__device__ int      g_binlo[BB];
__device__ int      g_rem[BB];
__device__ int      g_ccount[BB];
__device__ unsigned long long g_cand[(size_t)BB*CAP];
__device__ float    g_mapA[BB*3];
__device__ float    g_invAh[BB*3];

__device__ __forceinline__ float4 f4add(float4 a, float4 b){
    return make_float4(a.x+b.x, a.y+b.y, a.z+b.z, a.w+b.w);
}

// ---------- stage 1: guidance + channel-min + horizontal min15 (float4) ----------
// Row-0 blocks also zero the per-batch selection state (replaces k_init).
__global__ void k_prep_minh(const float* __restrict__ x){
    int row = blockIdx.x, b = blockIdx.y, t = threadIdx.x;  // t < 128
    if (row == 0){
        for (int i = t; i < NBIN; i += 128) g_hist4k[b*NBIN + i] = 0;
        if (t == 0) g_ccount[b] = 0;
    }
    const float4* xr = (const float4*)(x + (size_t)b*3*HWSZ + (size_t)row*WW);
    float4 r  = xr[t];
    float4 g  = xr[HWSZ/4 + t];
    float4 bl = xr[2*(HWSZ/4) + t];
    size_t o4 = ((size_t)b*HWSZ + (size_t)row*WW) >> 2;
    float4 gv;
    gv.x = (0.2989f*r.x + 0.587f*g.x + 0.114f*bl.x + 1.0f)*0.5f;
    gv.y = (0.2989f*r.y + 0.587f*g.y + 0.114f*bl.y + 1.0f)*0.5f;
    gv.z = (0.2989f*r.z + 0.587f*g.z + 0.114f*bl.z + 1.0f)*0.5f;
    gv.w = (0.2989f*r.w + 0.587f*g.w + 0.114f*bl.w + 1.0f)*0.5f;
    ((float4*)g_guid)[o4 + t] = gv;
    // min over channels of (v+1)/2 == (min over channels of v + 1)/2 (monotone, bit-safe)
    float4 mn;
    mn.x = (fminf(r.x, fminf(g.x, bl.x)) + 1.0f)*0.5f;
    mn.y = (fminf(r.y, fminf(g.y, bl.y)) + 1.0f)*0.5f;
    mn.z = (fminf(r.z, fminf(g.z, bl.z)) + 1.0f)*0.5f;
    mn.w = (fminf(r.w, fminf(g.w, bl.w)) + 1.0f)*0.5f;
    __shared__ float s[WW + 32];
    *(float4*)&s[16 + 4*t] = mn;
    if (t < 7){ s[9+t] = 1.0f; s[528+t] = 1.0f; }
    __syncthreads();
    const float* a = &s[4*t + 9];
    float c12 = a[3];
    #pragma unroll
    for (int j=4; j<=14; j++) c12 = fminf(c12, a[j]);
    float4 o;
    o.x = fminf(fminf(a[0], a[1]), fminf(a[2], c12));
    o.y = fminf(fminf(a[1], a[2]), fminf(c12, a[15]));
    o.z = fminf(a[2], fminf(c12, fminf(a[15], a[16])));
    o.w = fminf(c12, fminf(a[15], fminf(a[16], a[17])));
    ((float4*)g_hmin1)[o4 + t] = o;
}

// ---------- vertical min15 -> dc1 + fused 4096-bin histogram ----------
__global__ void k_minv0_hist(){
    int b  = blockIdx.z;
    int bx = blockIdx.x*32, by = blockIdx.y*128;
    int tx = threadIdx.x, ty = threadIdx.y;
    int tid = ty*32 + tx;
    __shared__ float s[142][32];
    __shared__ unsigned shh[NBIN];
    for (int i = tid; i < NBIN; i += 256) shh[i] = 0;
    const float* sb = g_hmin1 + (size_t)b*HWSZ;
    for (int i = tid; i < 142*8; i += 256){
        int rr = i >> 3, c4 = i & 7;
        int gy = by - 7 + rr;
        float4 v = (gy >= 0 && gy < HH)
                   ? ((const float4*)(sb + (size_t)gy*WW + bx))[c4]
                   : make_float4(1,1,1,1);
        *(float4*)&s[rr][c4*4] = v;
    }
    __syncthreads();
    float* db = g_dc1 + (size_t)b*HWSZ;
    #pragma unroll
    for (int o = 0; o < 16; o++){
        int ry = ty + o*8;
        float m = s[ry][tx];
        #pragma unroll
        for (int i = 1; i < 15; i++) m = fminf(m, s[ry+i][tx]);
        db[(size_t)(by+ry)*WW + bx + tx] = m;
        unsigned bin = min(4095u, (unsigned)(m * 16384.0f));
        unsigned mm = __match_any_sync(0xffffffffu, bin);
        if (tx == __ffs(mm)-1) atomicAdd(&shh[bin], (unsigned)__popc(mm));
    }
    __syncthreads();
    unsigned* gh = g_hist4k + b*NBIN;
    for (int i = tid; i < NBIN; i += 256)
        if (shh[i]) atomicAdd(&gh[i], shh[i]);
}

// ---------- scan histogram (parallel shuffle scan) ----------
__global__ void k_scan(){
    int b = blockIdx.x, t = threadIdx.x;
    const unsigned* h = g_hist4k + b*NBIN;
    int hi_bin = 4095 - t*16;
    unsigned v[16]; unsigned sum = 0;
    #pragma unroll
    for (int i = 0; i < 16; i++){ v[i] = h[hi_bin - i]; sum += v[i]; }
    unsigned lane = t & 31, wid = t >> 5;
    unsigned s = sum;
    #pragma unroll
    for (int o = 1; o < 32; o <<= 1){
        unsigned n = __shfl_up_sync(0xffffffffu, s, o);
        if (lane >= o) s += n;
    }
    __shared__ unsigned wsum[8];
    if (lane == 31) wsum[wid] = s;
    __syncthreads();
    unsigned woff = 0;
    #pragma unroll
    for (int w = 0; w < 8; w++) if (w < (int)wid) woff += wsum[w];
    unsigned cum = s + woff - sum;   // exclusive prefix in descending-bin order
    #pragma unroll
    for (int i = 0; i < 16; i++){
        unsigned c = v[i];
        if (cum < KSEL && cum + c >= KSEL){
            g_binlo[b] = hi_bin - i;
            g_rem[b]   = KSEL - (int)cum;
        }
        cum += c;
    }
}

// ---------- collect candidates (bin >= binlo) ----------
__global__ void k_collect(){
    int b = blockIdx.y;
    int binlo = g_binlo[b];
    const float4* dc = (const float4*)(g_dc1 + (size_t)b*HWSZ);
    unsigned long long* cb = g_cand + (size_t)b*CAP;
    for (int i = blockIdx.x*256 + threadIdx.x; i < HWSZ/4; i += 64*256){
        float4 v = dc[i];
        float vv[4] = {v.x, v.y, v.z, v.w};
        #pragma unroll
        for (int k = 0; k < 4; k++){
            unsigned bin = min(4095u, (unsigned)(vv[k]*16384.0f));
            if ((int)bin >= binlo){
                int pos = atomicAdd(&g_ccount[b], 1);
                if (pos < CAP)
                    cb[pos] = ((unsigned long long)__float_as_uint(vv[k]) << 32) | (unsigned)(i*4 + k);
            }
        }
    }
}

// ---------- exact select over candidates: radix for tau, tie cut, argmax ----------
__global__ void k_select(const float* __restrict__ x){
    int b = blockIdx.x, tid = threadIdx.x;
    int n = min(g_ccount[b], CAP);
    const unsigned long long* cand = g_cand + (size_t)b*CAP;

    __shared__ unsigned hist[256];
    __shared__ unsigned s_pref;
    __shared__ int s_rem;
    if (tid == 0){ s_pref = 0; s_rem = KSEL; }
    __syncthreads();
    for (int shift = 24; shift >= 0; shift -= 8){
        hist[tid] = 0;
        __syncthreads();
        unsigned pref = s_pref;
        for (int j = tid; j < n; j += 256){
            unsigned bits = (unsigned)(cand[j] >> 32);
            if (shift == 24 || (bits >> (shift+8)) == pref)
                atomicAdd(&hist[(bits >> shift) & 255u], 1u);
        }
        __syncthreads();
        if (tid == 0){
            int rem = s_rem, cum = 0, chosen = 0;
            for (int bin = 255; bin >= 0; --bin){
                int c = (int)hist[bin];
                if (cum + c >= rem){ chosen = bin; break; }
                cum += c;
            }
            s_pref = (pref << 8) | (unsigned)chosen;
            s_rem  = rem - cum;
        }
        __syncthreads();
    }
    unsigned tau = s_pref;
    int m = s_rem;                         // selected count within value==tau group

    // idx_cut = m-th smallest index among value==tau (top_k ties: lower index first)
    __shared__ int s_cnt;
    int lo = 0, hi = HWSZ - 1;
    while (lo < hi){
        int mid = (lo + hi) >> 1;
        if (tid == 0) s_cnt = 0;
        __syncthreads();
        int local = 0;
        for (int j = tid; j < n; j += 256){
            unsigned long long e = cand[j];
            if ((unsigned)(e >> 32) == tau && (int)(e & 0xffffffffu) <= mid) local++;
        }
        if (local) atomicAdd(&s_cnt, local);
        __syncthreads();
        int c = s_cnt;
        __syncthreads();
        if (c >= m) hi = mid; else lo = mid + 1;
    }
    int idx_cut = lo;

    // argmax intensity, tie-break by top_k order (value desc, index asc)
    float bi = -1e30f, bd = -1e30f; int bix = 0x7fffffff;
    const float* xb = x + (size_t)b*3*HWSZ;
    for (int j = tid; j < n; j += 256){
        unsigned long long e = cand[j];
        unsigned bits = (unsigned)(e >> 32);
        int idx = (int)(e & 0xffffffffu);
        if (bits > tau || (bits == tau && idx <= idx_cut)){
            float r  = (xb[idx]        + 1.0f)*0.5f;
            float g  = (xb[HWSZ+idx]   + 1.0f)*0.5f;
            float bl = (xb[2*HWSZ+idx] + 1.0f)*0.5f;
            float inten = 0.2989f*r + 0.587f*g + 0.114f*bl;
            float dv = __uint_as_float(bits);
            bool better = (inten > bi) ||
                          (inten == bi && (dv > bd || (dv == bd && idx < bix)));
            if (better){ bi = inten; bd = dv; bix = idx; }
        }
    }
    __shared__ float sI[256], sD[256];
    __shared__ int   sX[256];
    sI[tid] = bi; sD[tid] = bd; sX[tid] = bix;
    __syncthreads();
    for (int s = 128; s > 0; s >>= 1){
        if (tid < s){
            float oi = sI[tid+s], od = sD[tid+s]; int ox = sX[tid+s];
            bool better = (oi > sI[tid]) ||
                          (oi == sI[tid] && (od > sD[tid] || (od == sD[tid] && ox < sX[tid])));
            if (better){ sI[tid] = oi; sD[tid] = od; sX[tid] = ox; }
        }
        __syncthreads();
    }
    if (tid < 3){
        int idx = sX[0];
        float a  = (xb[(size_t)tid*HWSZ + idx] + 1.0f)*0.5f;
        float mA = a*2.0f - 1.0f;
        g_mapA[b*3+tid]  = mA;
        g_invAh[b*3+tid] = 1.0f / ((mA + 1.0f)*0.5f);
    }
}

// ---------- ratio channel-min + horizontal min15 (float4) ----------
__global__ void k_ratio_minh(const float* __restrict__ x){
    int row = blockIdx.x, b = blockIdx.y, t = threadIdx.x;  // t < 128
    const float4* xr = (const float4*)(x + (size_t)b*3*HWSZ + (size_t)row*WW);
    float inv0 = g_invAh[b*3], inv1 = g_invAh[b*3+1], inv2 = g_invAh[b*3+2];
    float4 r  = xr[t];
    float4 g  = xr[HWSZ/4 + t];
    float4 bl = xr[2*(HWSZ/4) + t];
    float4 mn;
    mn.x = fminf((r.x+1.0f)*0.5f*inv0, fminf((g.x+1.0f)*0.5f*inv1, (bl.x+1.0f)*0.5f*inv2));
    mn.y = fminf((r.y+1.0f)*0.5f*inv0, fminf((g.y+1.0f)*0.5f*inv1, (bl.y+1.0f)*0.5f*inv2));
    mn.z = fminf((r.z+1.0f)*0.5f*inv0, fminf((g.z+1.0f)*0.5f*inv1, (bl.z+1.0f)*0.5f*inv2));
    mn.w = fminf((r.w+1.0f)*0.5f*inv0, fminf((g.w+1.0f)*0.5f*inv1, (bl.w+1.0f)*0.5f*inv2));
    __shared__ float s[WW + 32];
    *(float4*)&s[16 + 4*t] = mn;
    if (t < 7){ s[9+t] = 1.0f; s[528+t] = 1.0f; }
    __syncthreads();
    const float* a = &s[4*t + 9];
    float c12 = a[3];
    #pragma unroll
    for (int j=4; j<=14; j++) c12 = fminf(c12, a[j]);
    float4 o;
    o.x = fminf(fminf(a[0], a[1]), fminf(a[2], c12));
    o.y = fminf(fminf(a[1], a[2]), fminf(c12, a[15]));
    o.z = fminf(a[2], fminf(c12, fminf(a[15], a[16])));
    o.w = fminf(c12, fminf(a[15], fminf(a[16], a[17])));
    ((float4*)g_hmin2)[(((size_t)b*HWSZ + (size_t)row*WW) >> 2) + t] = o;
}

// ---------- vertical min15 -> trans_raw p ----------
__global__ void k_minv1(){
    int b  = blockIdx.z;
    int bx = blockIdx.x*32, by = blockIdx.y*128;
    int tx = threadIdx.x, ty = threadIdx.y;
    int tid = ty*32 + tx;
    __shared__ float s[142][32];
    const float* sb = g_hmin2 + (size_t)b*HWSZ;
    for (int i = tid; i < 142*8; i += 256){
        int rr = i >> 3, c4 = i & 7;
        int gy = by - 7 + rr;
        float4 v = (gy >= 0 && gy < HH)
                   ? ((const float4*)(sb + (size_t)gy*WW + bx))[c4]
                   : make_float4(1,1,1,1);
        *(float4*)&s[rr][c4*4] = v;
    }
    __syncthreads();
    float* db = g_p + (size_t)b*HWSZ;
    #pragma unroll
    for (int o = 0; o < 16; o++){
        int ry = ty + o*8;
        float m = s[ry][tx];
        #pragma unroll
        for (int i = 1; i < 15; i++) m = fminf(m, s[ry+i][tx]);
        db[(size_t)(by+ry)*WW + bx + tx] = 1.0f - 0.95f*m;
    }
}

// ---------- guided filter: H box of (I,p,Ip,II), staged coalesced output ----------
// 2 rows/block to stay under the 48KB static smem limit.
__global__ void k_box4h(){
    int b    = blockIdx.z;
    int row0 = blockIdx.y*2;
    int tx = threadIdx.x, ty = threadIdx.y;   // (64,2)
    int tid = ty*64 + tx;
    __shared__ float sI[2][544], sp[2][544];
    __shared__ float4 so[2][512];
    const float4* I4 = (const float4*)(g_guid + (size_t)b*HWSZ + (size_t)(row0+ty)*WW);
    const float4* p4 = (const float4*)(g_p    + (size_t)b*HWSZ + (size_t)(row0+ty)*WW);
    for (int i = tx; i < 128; i += 64){
        *(float4*)&sI[ty][16 + 4*i] = I4[i];
        *(float4*)&sp[ty][16 + 4*i] = p4[i];
    }
    if (tx < 16){
        sI[ty][tx] = 0.f; sp[ty][tx] = 0.f;
        sI[ty][528+tx] = 0.f; sp[ty][528+tx] = 0.f;
    }
    __syncthreads();
    int c0 = tx*8;
    float4 acc = make_float4(0,0,0,0);
    #pragma unroll
    for (int i = 0; i < 31; i++){
        float Iv = sI[ty][c0+1+i], pv = sp[ty][c0+1+i];
        acc.x += Iv; acc.y += pv; acc.z += Iv*pv; acc.w += Iv*Iv;
    }
    so[ty][c0] = acc;
    #pragma unroll
    for (int j = 1; j < 8; j++){
        float Ia = sI[ty][c0+31+j], pa = sp[ty][c0+31+j];
        float Is = sI[ty][c0+j],    ps = sp[ty][c0+j];
        acc.x += Ia - Is; acc.y += pa - ps;
        acc.z += Ia*pa - Is*ps; acc.w += Ia*Ia - Is*Is;
        so[ty][c0+j] = acc;
    }
    __syncthreads();
    float4* dst = g_b4h + (size_t)b*HWSZ + (size_t)row0*WW;
    for (int i = tid; i < 1024; i += 128)
        dst[(size_t)(i>>9)*WW + (i & 511)] = so[i>>9][i & 511];
}

// ---------- guided filter: V box + a,b ----------
__global__ void k_box4v_ab(){
    int b  = blockIdx.z;
    int bx = blockIdx.x*32, by = blockIdx.y*64;
    int tx = threadIdx.x, ty = threadIdx.y;
    int tid = ty*32 + tx;
    __shared__ float4 s[94][32];
    const float4* sb = g_b4h + (size_t)b*HWSZ;
    for (int i = tid; i < 94*32; i += 256){
        int rr = i >> 5, cc = i & 31;
        int gy = by - 15 + rr;
        s[rr][cc] = (gy >= 0 && gy < HH) ? sb[(size_t)gy*WW + bx + cc] : make_float4(0,0,0,0);
    }
    __syncthreads();
    int gx = bx + tx;
    float fnx = (float)(min(gx+15, WW-1) - max(gx-15, 0) + 1);
    int r0 = ty*8;
    float4 acc = make_float4(0,0,0,0);
    #pragma unroll
    for (int i = 0; i < 31; i++) acc = f4add(acc, s[r0+i][tx]);
    float2* db = g_ab + (size_t)b*HWSZ;
    #pragma unroll
    for (int j = 0; j < 8; j++){
        if (j > 0){
            float4 va = s[r0+30+j][tx], vs = s[r0+j-1][tx];
            acc.x += va.x - vs.x; acc.y += va.y - vs.y;
            acc.z += va.z - vs.z; acc.w += va.w - vs.w;
        }
        int gy = by + r0 + j;
        float fny = (float)(min(gy+15, HH-1) - max(gy-15, 0) + 1);
        float nInv = __frcp_rn(fnx*fny);
        float mI = acc.x*nInv, mp = acc.y*nInv, mIp = acc.z*nInv, mII = acc.w*nInv;
        float cov = mIp - mI*mp;
        float var = mII - mI*mI;
        float a   = cov / (var + 1e-3f);
        float bb2 = mp - a*mI;
        db[(size_t)gy*WW + gx] = make_float2(a, bb2);
    }
}

// ---------- guided filter: H box of (a,b), staged coalesced output ----------
__global__ void k_abh(){
    int b    = blockIdx.z;
    int row0 = blockIdx.y*4;
    int tx = threadIdx.x, ty = threadIdx.y;  // (64,4)
    int tid = ty*64 + tx;
    __shared__ float sa[4][544], sb2[4][544];
    __shared__ float2 so[4][512];
    const float4* ab4 = (const float4*)(g_ab + (size_t)b*HWSZ + (size_t)(row0+ty)*WW);
    for (int i = tx; i < 256; i += 64){
        float4 v = ab4[i];
        sa [ty][16 + 2*i]   = v.x; sb2[ty][16 + 2*i]   = v.y;
        sa [ty][17 + 2*i]   = v.z; sb2[ty][17 + 2*i]   = v.w;
    }
    if (tx < 16){
        sa[ty][tx] = 0.f; sb2[ty][tx] = 0.f;
        sa[ty][528+tx] = 0.f; sb2[ty][528+tx] = 0.f;
    }
    __syncthreads();
    int c0 = tx*8;
    float2 acc = make_float2(0,0);
    #pragma unroll
    for (int i = 0; i < 31; i++){ acc.x += sa[ty][c0+1+i]; acc.y += sb2[ty][c0+1+i]; }
    so[ty][c0] = acc;
    #pragma unroll
    for (int j = 1; j < 8; j++){
        acc.x += sa [ty][c0+31+j] - sa [ty][c0+j];
        acc.y += sb2[ty][c0+31+j] - sb2[ty][c0+j];
        so[ty][c0+j] = acc;
    }
    __syncthreads();
    float2* dst = g_abh + (size_t)b*HWSZ + (size_t)row0*WW;
    const float4* sof = (const float4*)so;
    for (int i = tid; i < 1024; i += 256){
        int rr = i >> 8, cc = i & 255;
        ((float4*)(dst + (size_t)rr*WW))[cc] = sof[i];
    }
}

// ---------- guided filter: V box of (a,b) + T + J + A write ----------
__global__ void k_abv_final(const float* __restrict__ x, float* __restrict__ out){
    int b  = blockIdx.z;
    int bx = blockIdx.x*32, by = blockIdx.y*64;
    int tx = threadIdx.x, ty = threadIdx.y;
    int tid = ty*32 + tx;
    __shared__ float2 s[94][32];
    const float2* sb = g_abh + (size_t)b*HWSZ;
    for (int i = tid; i < 94*16; i += 256){
        int rr = i >> 4, c2 = (i & 15)*2;
        int gy = by - 15 + rr;
        float4 v = (gy >= 0 && gy < HH)
                   ? ((const float4*)(sb + (size_t)gy*WW + bx))[i & 15]
                   : make_float4(0,0,0,0);
        s[rr][c2]   = make_float2(v.x, v.y);
        s[rr][c2+1] = make_float2(v.z, v.w);
    }
    __syncthreads();
    int gx = bx + tx;
    float fnx = (float)(min(gx+15, WW-1) - max(gx-15, 0) + 1);
    float mA0 = g_mapA[b*3], mA1 = g_mapA[b*3+1], mA2 = g_mapA[b*3+2];
    int r0 = ty*8;
    float2 acc = make_float2(0,0);
    #pragma unroll
    for (int i = 0; i < 31; i++){ acc.x += s[r0+i][tx].x; acc.y += s[r0+i][tx].y; }
    float* outJ = out;
    float* outT = out + (size_t)BB*3*HWSZ;
    float* outA = out + (size_t)BB*3*HWSZ + (size_t)BB*HWSZ;
    const float* xb = x + (size_t)b*3*HWSZ;
    #pragma unroll
    for (int j = 0; j < 8; j++){
        if (j > 0){
            acc.x += s[r0+30+j][tx].x - s[r0+j-1][tx].x;
            acc.y += s[r0+30+j][tx].y - s[r0+j-1][tx].y;
        }
        int gy = by + r0 + j;
        float fny = (float)(min(gy+15, HH-1) - max(gy-15, 0) + 1);
        float nInv = __frcp_rn(fnx*fny);
        size_t idx = (size_t)gy*WW + gx;
        float I = g_guid[(size_t)b*HWSZ + idx];
        float T = (acc.x*nInv)*I + acc.y*nInv;
        outT[(size_t)b*HWSZ + idx] = T;
        float invT = 1.0f / T;
        float x0 = xb[idx], x1 = xb[HWSZ+idx], x2 = xb[2*HWSZ+idx];
        size_t jb = (size_t)b*3*HWSZ + idx;
        outJ[jb]          = ((x0+1.0f)*0.5f - mA0)*invT + mA0;
        outJ[jb+HWSZ]     = ((x1+1.0f)*0.5f - mA1)*invT + mA1;
        outJ[jb+2*HWSZ]   = ((x2+1.0f)*0.5f - mA2)*invT + mA2;
        outA[jb]          = mA0;
        outA[jb+HWSZ]     = mA1;
        outA[jb+2*HWSZ]   = mA2;
    }
}

// ---------------- launch ----------------
extern "C" void kernel_launch(void* const* d_in, const int* in_sizes, int n_in,
                              void* d_out, int out_size){
    (void)in_sizes; (void)n_in; (void)out_size;
    const float* x = (const float*)d_in[0];
    float* out = (float*)d_out;

    k_prep_minh<<<dim3(HH, BB), 128>>>(x);
    k_minv0_hist<<<dim3(16, 4, BB), dim3(32, 8)>>>();
    k_scan<<<BB, 256>>>();
    k_collect<<<dim3(64, BB), 256>>>();
    k_select<<<BB, 256>>>(x);

    k_ratio_minh<<<dim3(HH, BB), 128>>>(x);
    k_minv1<<<dim3(16, 4, BB), dim3(32, 8)>>>();

    k_box4h<<<dim3(1, HH/2, BB), dim3(64, 2)>>>();
    k_box4v_ab<<<dim3(WW/32, HH/64, BB), dim3(32, 8)>>>();
    k_abh<<<dim3(1, HH/4, BB), dim3(64, 4)>>>();
    k_abv_final<<<dim3(WW/32, HH/64, BB), dim3(32, 8)>>>(x, out);
}